// round 6
// baseline (speedup 1.0000x reference)
#include <cuda_runtime.h>

#define NN 100000
#define NE 800000
#define HID 256
#define BN 32

// Scratch (allocation-free rule: __device__ globals). 16B-aligned for float4 access.
__device__ __align__(16) float g_dinv[NN];
__device__ __align__(16) float g_hs[NN * BN];     // row-prescaled features
__device__ __align__(16) float g_agg[NN * BN];    // aggregation accumulator

// ---------------------------------------------------------------------------
// Degree / normalization
// ---------------------------------------------------------------------------
__global__ void k_init_deg() {
    int i = blockIdx.x * blockDim.x + threadIdx.x;
    if (i < NN) g_dinv[i] = 1.0f;     // self-loop contributes 1 to every degree
}

__global__ __launch_bounds__(256) void k_count_deg(const int* __restrict__ col) {
    for (int e = blockIdx.x * blockDim.x + threadIdx.x; e < NE;
         e += gridDim.x * blockDim.x)
        atomicAdd(&g_dinv[col[e]], 1.0f);
}

__global__ void k_finalize_dinv() {
    int i = blockIdx.x * blockDim.x + threadIdx.x;
    if (i < NN) g_dinv[i] = rsqrtf(g_dinv[i]);   // deg >= 1 always
}

// ---------------------------------------------------------------------------
// GEMM1: hs[n][k] = (sum_h x[n][h] * Wd[k][h]) * dinv[n]
//        agg[n][k] = hs[n][k] * dinv[n]          (self-loop init)
// ---------------------------------------------------------------------------
__global__ __launch_bounds__(256) void k_gemm_down(const float* __restrict__ x,
                                                   const float* __restrict__ Wd) {
    __shared__ __align__(16) float As[128 * 68];
    __shared__ __align__(16) float Bs[64 * 36];

    int tid = threadIdx.x;
    int cx = tid & 7;                 // 8 col-groups * 4 = 32 cols
    int ry = tid >> 3;                // 32 row-groups * 4 = 128 rows
    int rowbase = blockIdx.x * 128;

    float acc[4][4];
#pragma unroll
    for (int i = 0; i < 4; i++)
#pragma unroll
        for (int j = 0; j < 4; j++) acc[i][j] = 0.0f;

    for (int ch = 0; ch < 4; ch++) {
        int hbase = ch * 64;
#pragma unroll
        for (int q = 0; q < 8; q++) {
            int idx4 = tid + q * 256;
            int r = idx4 >> 4;
            int h4 = (idx4 & 15) << 2;
            float4 v = make_float4(0.f, 0.f, 0.f, 0.f);
            int gr = rowbase + r;
            if (gr < NN) v = *(const float4*)&x[gr * HID + hbase + h4];
            *(float4*)&As[r * 68 + h4] = v;
        }
#pragma unroll
        for (int q = 0; q < 8; q++) {
            int idx = tid + q * 256;
            int k = idx >> 6;
            int hh = idx & 63;
            Bs[hh * 36 + k] = Wd[k * HID + hbase + hh];
        }
        __syncthreads();

#pragma unroll 8
        for (int hh = 0; hh < 64; hh++) {
            float a0 = As[(ry * 4 + 0) * 68 + hh];
            float a1 = As[(ry * 4 + 1) * 68 + hh];
            float a2 = As[(ry * 4 + 2) * 68 + hh];
            float a3 = As[(ry * 4 + 3) * 68 + hh];
            float4 w = *(const float4*)&Bs[hh * 36 + cx * 4];
            acc[0][0] = fmaf(a0, w.x, acc[0][0]);
            acc[0][1] = fmaf(a0, w.y, acc[0][1]);
            acc[0][2] = fmaf(a0, w.z, acc[0][2]);
            acc[0][3] = fmaf(a0, w.w, acc[0][3]);
            acc[1][0] = fmaf(a1, w.x, acc[1][0]);
            acc[1][1] = fmaf(a1, w.y, acc[1][1]);
            acc[1][2] = fmaf(a1, w.z, acc[1][2]);
            acc[1][3] = fmaf(a1, w.w, acc[1][3]);
            acc[2][0] = fmaf(a2, w.x, acc[2][0]);
            acc[2][1] = fmaf(a2, w.y, acc[2][1]);
            acc[2][2] = fmaf(a2, w.z, acc[2][2]);
            acc[2][3] = fmaf(a2, w.w, acc[2][3]);
            acc[3][0] = fmaf(a3, w.x, acc[3][0]);
            acc[3][1] = fmaf(a3, w.y, acc[3][1]);
            acc[3][2] = fmaf(a3, w.z, acc[3][2]);
            acc[3][3] = fmaf(a3, w.w, acc[3][3]);
        }
        __syncthreads();
    }

#pragma unroll
    for (int i = 0; i < 4; i++) {
        int r = rowbase + ry * 4 + i;
        if (r < NN) {
            float di = g_dinv[r];
            float4 hsv;
            hsv.x = acc[i][0] * di;
            hsv.y = acc[i][1] * di;
            hsv.z = acc[i][2] * di;
            hsv.w = acc[i][3] * di;
            *(float4*)&g_hs[r * BN + cx * 4] = hsv;
            float4 ag = make_float4(hsv.x * di, hsv.y * di, hsv.z * di, hsv.w * di);
            *(float4*)&g_agg[r * BN + cx * 4] = ag;
        }
    }
}

// ---------------------------------------------------------------------------
// Edge scatter: agg[col] += hs[row] * dinv[col]   (8 lanes/edge, float4 gather,
// 4 scalar no-return atomicAdd -> REDG per lane)
// ---------------------------------------------------------------------------
__global__ __launch_bounds__(256) void k_scatter(const int* __restrict__ rows,
                                                 const int* __restrict__ cols) {
    int t = blockIdx.x * 256 + threadIdx.x;
    int e = t >> 3;
    if (e >= NE) return;
    int j = t & 7;
    int r = rows[e];
    int c = cols[e];
    float dc = __ldg(&g_dinv[c]);
    float4 v = __ldg(((const float4*)g_hs) + (r * 8 + j));
    float* dst = &g_agg[c * BN + j * 4];
    atomicAdd(dst + 0, v.x * dc);
    atomicAdd(dst + 1, v.y * dc);
    atomicAdd(dst + 2, v.z * dc);
    atomicAdd(dst + 3, v.w * dc);
}

// ---------------------------------------------------------------------------
// ReLU + bias, then pre-scale for conv2 and re-init agg with its self-loop
// ---------------------------------------------------------------------------
__global__ __launch_bounds__(256) void k_relu_stage(const float* __restrict__ bd) {
    int i = blockIdx.x * blockDim.x + threadIdx.x;   // < NN*BN
    int n = i >> 5;
    float di = g_dinv[n];
    float v = fmaxf(g_agg[i] + bd[i & 31], 0.0f) * di;  // h1 * dinv[n]
    g_hs[i] = v;
    g_agg[i] = v * di;                                   // self-loop init
}

// ---------------------------------------------------------------------------
// GEMM2 + epilogue: out[n][h] = sum_k agg[n][k] * Wu[h][k] + bu[h] + x[n][h]
// ---------------------------------------------------------------------------
__global__ __launch_bounds__(256) void k_gemm_up(const float* __restrict__ x,
                                                 const float* __restrict__ Wu,
                                                 const float* __restrict__ bu,
                                                 float* __restrict__ out) {
    __shared__ __align__(16) float Bs2[32 * 260];   // Bs2[k][h] = Wu[h][k]
    __shared__ __align__(16) float As2[16 * 33];

    int tid = threadIdx.x;
    int cx = tid & 63;                // 64 col-groups * 4 = 256 cols
    int ry = tid >> 6;                // 4 row-groups * 4 = 16 rows per tile
    int blockrow = blockIdx.x * 128;

#pragma unroll
    for (int q = 0; q < 32; q++) {
        int idx = tid + q * 256;      // 0..8191
        int h = idx >> 5;
        int k = idx & 31;
        Bs2[k * 260 + h] = Wu[idx];
    }

    float4 b4 = *(const float4*)&bu[cx * 4];

    for (int t = 0; t < 8; t++) {
        int rb = blockrow + t * 16;
        __syncthreads();
#pragma unroll
        for (int q = 0; q < 2; q++) {
            int id = tid + q * 256;
            int r = id >> 5;
            int k = id & 31;
            int gr = rb + r;
            As2[r * 33 + k] = (gr < NN) ? g_agg[gr * BN + k] : 0.0f;
        }
        __syncthreads();

        float acc[4][4];
#pragma unroll
        for (int i = 0; i < 4; i++)
#pragma unroll
            for (int j = 0; j < 4; j++) acc[i][j] = 0.0f;

#pragma unroll
        for (int k = 0; k < 32; k++) {
            float a0 = As2[(ry * 4 + 0) * 33 + k];
            float a1 = As2[(ry * 4 + 1) * 33 + k];
            float a2 = As2[(ry * 4 + 2) * 33 + k];
            float a3 = As2[(ry * 4 + 3) * 33 + k];
            float4 w = *(const float4*)&Bs2[k * 260 + cx * 4];
            acc[0][0] = fmaf(a0, w.x, acc[0][0]);
            acc[0][1] = fmaf(a0, w.y, acc[0][1]);
            acc[0][2] = fmaf(a0, w.z, acc[0][2]);
            acc[0][3] = fmaf(a0, w.w, acc[0][3]);
            acc[1][0] = fmaf(a1, w.x, acc[1][0]);
            acc[1][1] = fmaf(a1, w.y, acc[1][1]);
            acc[1][2] = fmaf(a1, w.z, acc[1][2]);
            acc[1][3] = fmaf(a1, w.w, acc[1][3]);
            acc[2][0] = fmaf(a2, w.x, acc[2][0]);
            acc[2][1] = fmaf(a2, w.y, acc[2][1]);
            acc[2][2] = fmaf(a2, w.z, acc[2][2]);
            acc[2][3] = fmaf(a2, w.w, acc[2][3]);
            acc[3][0] = fmaf(a3, w.x, acc[3][0]);
            acc[3][1] = fmaf(a3, w.y, acc[3][1]);
            acc[3][2] = fmaf(a3, w.z, acc[3][2]);
            acc[3][3] = fmaf(a3, w.w, acc[3][3]);
        }

#pragma unroll
        for (int i = 0; i < 4; i++) {
            int r = rb + ry * 4 + i;
            if (r < NN) {
                float4 xv = *(const float4*)&x[r * HID + cx * 4];
                float4 o;
                o.x = acc[i][0] + b4.x + xv.x;
                o.y = acc[i][1] + b4.y + xv.y;
                o.z = acc[i][2] + b4.z + xv.z;
                o.w = acc[i][3] + b4.w + xv.w;
                *(float4*)&out[r * HID + cx * 4] = o;
            }
        }
    }
}

// ---------------------------------------------------------------------------
extern "C" void kernel_launch(void* const* d_in, const int* in_sizes, int n_in,
                              void* d_out, int out_size) {
    // Resolve inputs by element count (robust to metadata ordering).
    // NOTE: edge_index is int32 (JAX x64 disabled -> int64 request yields int32).
    const float* x = 0; const int* ei = 0;
    const float* Wd = 0; const float* bd = 0;
    const float* Wu = 0; const float* bu = 0;
    for (int i = 0; i < n_in; i++) {
        int sz = in_sizes[i];
        if (sz == NN * HID)       x  = (const float*)d_in[i];
        else if (sz == 2 * NE)    ei = (const int*)d_in[i];
        else if (sz == BN * HID) { if (!Wd) Wd = (const float*)d_in[i];
                                   else     Wu = (const float*)d_in[i]; }
        else if (sz == BN)        bd = (const float*)d_in[i];
        else if (sz == HID)       bu = (const float*)d_in[i];
    }
    float* out = (float*)d_out;

    const int* erow = ei;        // edge_index[0] = source
    const int* ecol = ei + NE;   // edge_index[1] = target

    k_init_deg<<<(NN + 255) / 256, 256>>>();
    k_count_deg<<<592, 256>>>(ecol);
    k_finalize_dinv<<<(NN + 255) / 256, 256>>>();

    k_gemm_down<<<(NN + 127) / 128, 256>>>(x, Wd);
    k_scatter<<<(NE * 8) / 256, 256>>>(erow, ecol);
    k_relu_stage<<<(NN * BN) / 256, 256>>>(bd);
    k_scatter<<<(NE * 8) / 256, 256>>>(erow, ecol);
    k_gemm_up<<<(NN + 127) / 128, 256>>>(x, Wu, bu, out);
}

// round 7
// speedup vs baseline: 1.3244x; 1.3244x over previous
#include <cuda_runtime.h>

#define NN 100000
#define NE 800000
#define HID 256
#define BN 32

typedef unsigned long long u64;

// Scratch (allocation-free rule: __device__ globals). 16B-aligned for float4 access.
__device__ __align__(16) float g_dinv[NN];
__device__ __align__(16) float g_hs[NN * BN];     // row-prescaled features
__device__ __align__(16) float g_agg[NN * BN];    // aggregation accumulator

// ---- f32x2 packed helpers -------------------------------------------------
__device__ __forceinline__ u64 pk2(float lo, float hi) {
    u64 r; asm("mov.b64 %0, {%1, %2};" : "=l"(r) : "f"(lo), "f"(hi)); return r;
}
__device__ __forceinline__ void upk2(float& lo, float& hi, u64 v) {
    asm("mov.b64 {%0, %1}, %2;" : "=f"(lo), "=f"(hi) : "l"(v));
}
__device__ __forceinline__ void ffma2(u64& d, u64 a, u64 b) {
    asm("fma.rn.f32x2 %0, %1, %2, %0;" : "+l"(d) : "l"(a), "l"(b));
}

// ---------------------------------------------------------------------------
// Degree / normalization
// ---------------------------------------------------------------------------
__global__ void k_init_deg() {
    int i = blockIdx.x * blockDim.x + threadIdx.x;
    if (i < NN) g_dinv[i] = 1.0f;     // self-loop contributes 1 to every degree
}

__global__ __launch_bounds__(256) void k_count_deg(const int* __restrict__ col) {
    for (int e = blockIdx.x * blockDim.x + threadIdx.x; e < NE;
         e += gridDim.x * blockDim.x)
        atomicAdd(&g_dinv[col[e]], 1.0f);
}

__global__ void k_finalize_dinv() {
    int i = blockIdx.x * blockDim.x + threadIdx.x;
    if (i < NN) g_dinv[i] = rsqrtf(g_dinv[i]);   // deg >= 1 always
}

// ---------------------------------------------------------------------------
// GEMM1: hs[n][k] = (sum_h x[n][h] * Wd[k][h]) * dinv[n]
//        agg[n][k] = hs[n][k] * dinv[n]          (self-loop init)
// 256 rows/block, 8x4 register tile (packed f32x2), H chunked by 32.
// ---------------------------------------------------------------------------
__global__ __launch_bounds__(256) void k_gemm_down(const float* __restrict__ x,
                                                   const float* __restrict__ Wd) {
    __shared__ __align__(16) float As[256 * 33];   // [r][hh], pad 33 (conflict-free a)
    __shared__ __align__(16) float Bs[32 * 36];    // [hh][k],  pad 36

    int tid = threadIdx.x;
    int cx = tid & 7;                 // 8 col-groups * 4 = 32 cols
    int ry = tid >> 3;                // 32 row-groups * 8 = 256 rows
    int rowbase = blockIdx.x * 256;

    u64 acc01[8], acc23[8];
#pragma unroll
    for (int i = 0; i < 8; i++) { acc01[i] = 0ULL; acc23[i] = 0ULL; }

    for (int ch = 0; ch < 8; ch++) {
        int hbase = ch * 32;
        // stage A: 256 rows x 32 floats (2048 float4 loads, scalar STS)
#pragma unroll
        for (int q = 0; q < 8; q++) {
            int idx4 = tid + q * 256;
            int r = idx4 >> 3;                  // 8 float4 per row
            int h4 = (idx4 & 7) << 2;
            float4 v = make_float4(0.f, 0.f, 0.f, 0.f);
            int gr = rowbase + r;
            if (gr < NN) v = *(const float4*)&x[gr * HID + hbase + h4];
            As[r * 33 + h4 + 0] = v.x;
            As[r * 33 + h4 + 1] = v.y;
            As[r * 33 + h4 + 2] = v.z;
            As[r * 33 + h4 + 3] = v.w;
        }
        // stage B: 32x32, coalesced global read, transposed store
        {
            int idx = tid;
#pragma unroll
            for (int q = 0; q < 4; q++) {
                int id = idx + q * 256;         // 0..1023
                int k = id >> 5;
                int hh = id & 31;
                Bs[hh * 36 + k] = Wd[k * HID + hbase + hh];
            }
        }
        __syncthreads();

#pragma unroll 8
        for (int hh = 0; hh < 32; hh++) {
            u64 w01 = *(const u64*)&Bs[hh * 36 + cx * 4];
            u64 w23 = *(const u64*)&Bs[hh * 36 + cx * 4 + 2];
#pragma unroll
            for (int i = 0; i < 8; i++) {
                float a = As[(ry * 8 + i) * 33 + hh];
                u64 a2 = pk2(a, a);
                ffma2(acc01[i], a2, w01);
                ffma2(acc23[i], a2, w23);
            }
        }
        __syncthreads();
    }

#pragma unroll
    for (int i = 0; i < 8; i++) {
        int r = rowbase + ry * 8 + i;
        if (r < NN) {
            float di = g_dinv[r];
            float4 hsv;
            upk2(hsv.x, hsv.y, acc01[i]);
            upk2(hsv.z, hsv.w, acc23[i]);
            hsv.x *= di; hsv.y *= di; hsv.z *= di; hsv.w *= di;
            *(float4*)&g_hs[r * BN + cx * 4] = hsv;
            float4 ag = make_float4(hsv.x * di, hsv.y * di, hsv.z * di, hsv.w * di);
            *(float4*)&g_agg[r * BN + cx * 4] = ag;
        }
    }
}

// ---------------------------------------------------------------------------
// Edge scatter: agg[col] += hs[row] * dinv[col]
// 8 lanes/edge: one float4 gather + one red.global.add.v4.f32 per lane.
// ---------------------------------------------------------------------------
__global__ __launch_bounds__(256) void k_scatter(const int* __restrict__ rows,
                                                 const int* __restrict__ cols) {
    int t = blockIdx.x * 256 + threadIdx.x;
    int e = t >> 3;
    if (e >= NE) return;
    int j = t & 7;
    int r = rows[e];
    int c = cols[e];
    float dc = __ldg(&g_dinv[c]);
    float4 v = __ldg(((const float4*)g_hs) + (r * 8 + j));
    float4* dst = ((float4*)g_agg) + (c * 8 + j);
    asm volatile("red.global.add.v4.f32 [%0], {%1, %2, %3, %4};"
                 :: "l"(dst), "f"(v.x * dc), "f"(v.y * dc), "f"(v.z * dc), "f"(v.w * dc)
                 : "memory");
}

// ---------------------------------------------------------------------------
// ReLU + bias (float4), then pre-scale for conv2 and re-init agg w/ self-loop
// ---------------------------------------------------------------------------
__global__ __launch_bounds__(256) void k_relu_stage(const float* __restrict__ bd) {
    int i4 = blockIdx.x * blockDim.x + threadIdx.x;   // < NN*BN/4
    int n = i4 >> 3;
    float di = g_dinv[n];
    float4 a = ((const float4*)g_agg)[i4];
    float4 b = ((const float4*)bd)[i4 & 7];
    float4 v;
    v.x = fmaxf(a.x + b.x, 0.0f) * di;
    v.y = fmaxf(a.y + b.y, 0.0f) * di;
    v.z = fmaxf(a.z + b.z, 0.0f) * di;
    v.w = fmaxf(a.w + b.w, 0.0f) * di;
    ((float4*)g_hs)[i4] = v;
    float4 ag = make_float4(v.x * di, v.y * di, v.z * di, v.w * di);
    ((float4*)g_agg)[i4] = ag;
}

// ---------------------------------------------------------------------------
// GEMM2 + epilogue: out[n][h] = sum_k agg[n][k] * Wu[h][k] + bu[h] + x[n][h]
// 128 rows/block (4 tiles of 32 rows), 8x4 register tile (packed f32x2).
// ---------------------------------------------------------------------------
__global__ __launch_bounds__(256) void k_gemm_up(const float* __restrict__ x,
                                                 const float* __restrict__ Wu,
                                                 const float* __restrict__ bu,
                                                 float* __restrict__ out) {
    __shared__ __align__(16) float Bs2[32 * 260];   // [k][h] = Wu[h][k]
    __shared__ __align__(16) float As2[32 * 33];    // agg tile [r][k], pad 33

    int tid = threadIdx.x;
    int cx = tid & 63;                // 64 col-groups * 4 = 256 cols
    int ry = tid >> 6;                // 4 row-groups * 8 = 32 rows per tile
    int blockrow = blockIdx.x * 128;

    // stage weights once per block (coalesced reads; transposed stores)
#pragma unroll
    for (int q = 0; q < 32; q++) {
        int idx = tid + q * 256;      // 0..8191
        int h = idx >> 5;
        int k = idx & 31;
        Bs2[k * 260 + h] = Wu[idx];
    }

    float4 b4 = *(const float4*)&bu[cx * 4];

    for (int t = 0; t < 4; t++) {
        int rb = blockrow + t * 32;
        __syncthreads();
        // stage agg tile: 32 rows x 32 k (coalesced both sides)
#pragma unroll
        for (int q = 0; q < 4; q++) {
            int id = tid + q * 256;   // 0..1023
            int r = id >> 5;
            int k = id & 31;
            int gr = rb + r;
            As2[r * 33 + k] = (gr < NN) ? g_agg[gr * BN + k] : 0.0f;
        }
        __syncthreads();

        u64 acc01[8], acc23[8];
#pragma unroll
        for (int i = 0; i < 8; i++) { acc01[i] = 0ULL; acc23[i] = 0ULL; }

#pragma unroll 8
        for (int k = 0; k < 32; k++) {
            u64 w01 = *(const u64*)&Bs2[k * 260 + cx * 4];
            u64 w23 = *(const u64*)&Bs2[k * 260 + cx * 4 + 2];
#pragma unroll
            for (int i = 0; i < 8; i++) {
                float a = As2[(ry * 8 + i) * 33 + k];
                u64 a2 = pk2(a, a);
                ffma2(acc01[i], a2, w01);
                ffma2(acc23[i], a2, w23);
            }
        }

#pragma unroll
        for (int i = 0; i < 8; i++) {
            int r = rb + ry * 8 + i;
            if (r < NN) {
                float4 xv = *(const float4*)&x[r * HID + cx * 4];
                float4 o;
                upk2(o.x, o.y, acc01[i]);
                upk2(o.z, o.w, acc23[i]);
                o.x += b4.x + xv.x;
                o.y += b4.y + xv.y;
                o.z += b4.z + xv.z;
                o.w += b4.w + xv.w;
                *(float4*)&out[r * HID + cx * 4] = o;
            }
        }
    }
}

// ---------------------------------------------------------------------------
extern "C" void kernel_launch(void* const* d_in, const int* in_sizes, int n_in,
                              void* d_out, int out_size) {
    // Resolve inputs by element count (robust to metadata ordering).
    // edge_index is int32 (JAX x64 disabled -> int64 request yields int32).
    const float* x = 0; const int* ei = 0;
    const float* Wd = 0; const float* bd = 0;
    const float* Wu = 0; const float* bu = 0;
    for (int i = 0; i < n_in; i++) {
        int sz = in_sizes[i];
        if (sz == NN * HID)       x  = (const float*)d_in[i];
        else if (sz == 2 * NE)    ei = (const int*)d_in[i];
        else if (sz == BN * HID) { if (!Wd) Wd = (const float*)d_in[i];
                                   else     Wu = (const float*)d_in[i]; }
        else if (sz == BN)        bd = (const float*)d_in[i];
        else if (sz == HID)       bu = (const float*)d_in[i];
    }
    float* out = (float*)d_out;

    const int* erow = ei;        // edge_index[0] = source
    const int* ecol = ei + NE;   // edge_index[1] = target

    k_init_deg<<<(NN + 255) / 256, 256>>>();
    k_count_deg<<<592, 256>>>(ecol);
    k_finalize_dinv<<<(NN + 255) / 256, 256>>>();

    k_gemm_down<<<(NN + 255) / 256, 256>>>(x, Wd);
    k_scatter<<<(NE * 8) / 256, 256>>>(erow, ecol);
    k_relu_stage<<<(NN * BN / 4 + 255) / 256, 256>>>(bd);
    k_scatter<<<(NE * 8) / 256, 256>>>(erow, ecol);
    k_gemm_up<<<(NN + 127) / 128, 256>>>(x, Wu, bu, out);
}